// round 2
// baseline (speedup 1.0000x reference)
#include <cuda_runtime.h>
#include <math.h>

#define Nn 16
#define Ss 4
#define Cc 128
#define Hh 36
#define Ww 36
#define Uu 8000
#define Rr 4
#define HW (Hh*Ww)
#define NKEY (37*37)   // 1369 bilinear cells (floor index in [-1,35] per axis)

// Scratch (device globals — no runtime allocation)
__device__ float g_coreT[(size_t)Nn*Ss*HW*Cc];   // [n][s][p][c], 42.5 MB
__device__ int   g_counts[NKEY];
__device__ int   g_offsets[NKEY+1];
__device__ int   g_cursor[NKEY];
__device__ int   g_sortedU[Uu];

// ---------------------------------------------------------------------------
// 1) Transpose core [n, s*C, h, w] -> coreT [n, s, p, c]  (channels-last)
// ---------------------------------------------------------------------------
__global__ void transpose_kernel(const float* __restrict__ core) {
    __shared__ float tile[32][33];
    int ns = blockIdx.z;            // n*S + s
    int c0 = blockIdx.y * 32;       // channel tile
    int p0 = blockIdx.x * 32;       // pixel tile
    int tx = threadIdx.x, ty = threadIdx.y;

    int c = c0 + ty, p = p0 + tx;
    if (p < HW) tile[ty][tx] = core[((size_t)ns*Cc + c)*HW + p];
    __syncthreads();
    int pw = p0 + ty, cw = c0 + tx;
    if (pw < HW) g_coreT[((size_t)ns*HW + pw)*Cc + cw] = tile[tx][ty];
}

// ---------------------------------------------------------------------------
// 2-4) Counting sort of u by bilinear cell
// ---------------------------------------------------------------------------
__device__ __forceinline__ int cell_key(const float* pos, int u) {
    float x = ((pos[2*u]   + 1.0f) * (float)Ww - 1.0f) * 0.5f;
    float y = ((pos[2*u+1] + 1.0f) * (float)Hh - 1.0f) * 0.5f;
    int kx = (int)floorf(x); kx = max(-1, min(kx, Ww-1));
    int ky = (int)floorf(y); ky = max(-1, min(ky, Hh-1));
    return (ky+1)*37 + (kx+1);
}

__global__ void zero_kernel() {
    int i = blockIdx.x*blockDim.x + threadIdx.x;
    if (i < NKEY) g_counts[i] = 0;
}

__global__ void count_kernel(const float* __restrict__ pos) {
    int u = blockIdx.x*blockDim.x + threadIdx.x;
    if (u >= Uu) return;
    atomicAdd(&g_counts[cell_key(pos, u)], 1);
}

__global__ void scan_kernel() {
    __shared__ int bufA[2048], bufB[2048];
    int t = threadIdx.x;
    for (int i = t; i < 2048; i += 1024) bufA[i] = (i < NKEY) ? g_counts[i] : 0;
    __syncthreads();
    int* src = bufA; int* dst = bufB;
    for (int off = 1; off < 2048; off <<= 1) {
        for (int i = t; i < 2048; i += 1024)
            dst[i] = src[i] + ((i >= off) ? src[i-off] : 0);
        __syncthreads();
        int* tmp = src; src = dst; dst = tmp;
    }
    // src = inclusive scan
    for (int i = t; i < NKEY; i += 1024) {
        g_offsets[i+1] = src[i];
        g_cursor[i]    = (i == 0) ? 0 : src[i-1];
    }
    if (t == 0) g_offsets[0] = 0;
}

__global__ void scatter_kernel(const float* __restrict__ pos) {
    int u = blockIdx.x*blockDim.x + threadIdx.x;
    if (u >= Uu) return;
    int p = atomicAdd(&g_cursor[cell_key(pos, u)], 1);
    g_sortedU[p] = u;
}

// ---------------------------------------------------------------------------
// 5) Main: one block per (cell, s). Corner data lives in registers for the
//    whole block (loaded once); loop over u's binned in this cell.
//    Thread layout: n = tid>>4 (16 batch items), sub = tid&15 (8-ch chunk).
// ---------------------------------------------------------------------------
__global__ void __launch_bounds__(256, 4)
main_kernel(const float* __restrict__ positions,
            const float* __restrict__ feature,
            const float* __restrict__ bias,
            float* __restrict__ out)
{
    int cell = blockIdx.x;
    int s    = blockIdx.y;
    int start = g_offsets[cell];
    int end   = g_offsets[cell+1];
    if (start == end) return;

    int cx = cell % 37 - 1;
    int cy = cell / 37 - 1;
    int x0 = max(cx, 0), x1 = min(cx+1, Ww-1);
    int y0 = max(cy, 0), y1 = min(cy+1, Hh-1);
    int pix0 = y0*Ww + x0;   // weight (1-wx)(1-wy)
    int pix1 = y0*Ww + x1;   // weight  wx  (1-wy)
    int pix2 = y1*Ww + x0;   // weight (1-wx) wy
    int pix3 = y1*Ww + x1;   // weight  wx   wy

    int t   = threadIdx.x;
    int n   = t >> 4;
    int sub = t & 15;

    // One-time load: 4 corners x 8 channels into registers (coalesced float4s)
    const float* baseT = g_coreT + ((size_t)(n*Ss + s))*HW*Cc + sub*8;
    float4 cv[4][2];
    {
        const float4* p0 = (const float4*)(baseT + (size_t)pix0*Cc);
        const float4* p1 = (const float4*)(baseT + (size_t)pix1*Cc);
        const float4* p2 = (const float4*)(baseT + (size_t)pix2*Cc);
        const float4* p3 = (const float4*)(baseT + (size_t)pix3*Cc);
        cv[0][0] = p0[0]; cv[0][1] = p0[1];
        cv[1][0] = p1[0]; cv[1][1] = p1[1];
        cv[2][0] = p2[0]; cv[2][1] = p2[1];
        cv[3][0] = p3[0]; cv[3][1] = p3[1];
    }

    __shared__ float smF[Rr*Cc];   // feature[s][u][:][:] for current u (2 KB)

    for (int idx = start; idx < end; idx++) {
        int u = g_sortedU[idx];

        __syncthreads();   // previous iteration finished reading smF
        {
            const float4* f4 = (const float4*)(feature + ((size_t)(s*Uu + u))*Rr*Cc);
            if (t < 128) ((float4*)smF)[t] = f4[t];
        }
        __syncthreads();

        float px = positions[2*u], py = positions[2*u+1];
        float x  = ((px + 1.0f) * (float)Ww - 1.0f) * 0.5f;
        float y  = ((py + 1.0f) * (float)Hh - 1.0f) * 0.5f;
        float wx = x - floorf(x);
        float wy = y - floorf(y);
        float w00 = (1.0f - wx) * (1.0f - wy);
        float w01 = wx * (1.0f - wy);
        float w10 = (1.0f - wx) * wy;
        float w11 = wx * wy;

        float acc0 = 0.f, acc1 = 0.f, acc2 = 0.f, acc3 = 0.f;
        #pragma unroll
        for (int j = 0; j < 2; j++) {
            float4 sv;
            sv.x = w00*cv[0][j].x + w01*cv[1][j].x + w10*cv[2][j].x + w11*cv[3][j].x;
            sv.y = w00*cv[0][j].y + w01*cv[1][j].y + w10*cv[2][j].y + w11*cv[3][j].y;
            sv.z = w00*cv[0][j].z + w01*cv[1][j].z + w10*cv[2][j].z + w11*cv[3][j].z;
            sv.w = w00*cv[0][j].w + w01*cv[1][j].w + w10*cv[2][j].w + w11*cv[3][j].w;

            int fi = sub*2 + j;
            float4 f0 = ((const float4*)(smF + 0*Cc))[fi];
            float4 f1 = ((const float4*)(smF + 1*Cc))[fi];
            float4 f2 = ((const float4*)(smF + 2*Cc))[fi];
            float4 f3 = ((const float4*)(smF + 3*Cc))[fi];
            acc0 += f0.x*sv.x + f0.y*sv.y + f0.z*sv.z + f0.w*sv.w;
            acc1 += f1.x*sv.x + f1.y*sv.y + f1.z*sv.z + f1.w*sv.w;
            acc2 += f2.x*sv.x + f2.y*sv.y + f2.z*sv.z + f2.w*sv.w;
            acc3 += f3.x*sv.x + f3.y*sv.y + f3.z*sv.z + f3.w*sv.w;
        }

        // reduce across the 16 sub-threads (width-16 groups keep the two
        // n's within a warp independent)
        #pragma unroll
        for (int d = 8; d > 0; d >>= 1) {
            acc0 += __shfl_down_sync(0xffffffffu, acc0, d, 16);
            acc1 += __shfl_down_sync(0xffffffffu, acc1, d, 16);
            acc2 += __shfl_down_sync(0xffffffffu, acc2, d, 16);
            acc3 += __shfl_down_sync(0xffffffffu, acc3, d, 16);
        }

        if (sub == 0) {
            float*       o  = out  + (((size_t)(n*Ss + s))*Uu + u)*Rr;
            const float* bb = bias + ((size_t)(s*Uu + u))*Rr;
            o[0] = acc0 + bb[0];
            o[1] = acc1 + bb[1];
            o[2] = acc2 + bb[2];
            o[3] = acc3 + bb[3];
        }
    }
}

// ---------------------------------------------------------------------------
extern "C" void kernel_launch(void* const* d_in, const int* in_sizes, int n_in,
                              void* d_out, int out_size) {
    const float* core      = (const float*)d_in[0];
    const float* positions = (const float*)d_in[1];
    const float* feature   = (const float*)d_in[2];
    const float* bias      = (const float*)d_in[3];
    float* out = (float*)d_out;

    dim3 tb(32, 32);
    dim3 tg((HW + 31)/32, Cc/32, Nn*Ss);
    transpose_kernel<<<tg, tb>>>(core);

    zero_kernel<<<(NKEY + 255)/256, 256>>>();
    count_kernel<<<(Uu + 255)/256, 256>>>(positions);
    scan_kernel<<<1, 1024>>>();
    scatter_kernel<<<(Uu + 255)/256, 256>>>(positions);

    main_kernel<<<dim3(NKEY, Ss), 256>>>(positions, feature, bias, out);
}